// round 10
// baseline (speedup 1.0000x reference)
#include <cuda_runtime.h>
#include <cuda_fp16.h>
#include <cstdint>

#define NMAX   100000
#define HWORDS 50000          // packed uint16x2 degree words
#define RDIV   14286          // nodes per dst-range (7*14286 >= 100000)
#define NR     7
#define SL     21             // slices per range: 7*21 = 147 blocks
#define BCAP   1000000        // bucket capacity (true ~914K +- 1K)
#define DB_BLOCKS 148
#define DB_TPB    512
#define NWARPS (DB_BLOCKS * (DB_TPB / 32))  // 2368

// Scratch (device globals; no allocation allowed)
__device__ uint32_t g_bcur[8];
__device__ __align__(16) uint32_t g_bin[NR * BCAP];        // packed (dl<<17)|src
__device__ __align__(16) uint32_t g_dpart[DB_BLOCKS * HWORDS];  // per-block deg hists
__device__ float    g_dinv[NMAX];
__device__ __align__(16) float   g_pf[NMAX];               // layer-1 values (fp32)
__device__ __align__(16) float2  g_rf[NMAX];               // layer-2 values (fp32, self-loop)
__device__ __align__(16) __half2 g_rh[NMAX];               // layer-2 values (half2, gathers)
__device__ __align__(16) float   g_part1[SL * NMAX];       // agg1 slice partials
__device__ __align__(16) float2  g_part2[SL * NMAX];       // agg2 slice partials

__global__ void k_init() {
    if (threadIdx.x < 8) g_bcur[threadIdx.x] = 0u;
}

// ---- fused degree histogram + dst-range binning (warp-owned chunks) ----

__global__ void k_degbin(const int* __restrict__ src, const int* __restrict__ dst,
                         int E, int chunk) {
    extern __shared__ uint32_t hist[];  // HWORDS = 200KB
    for (int i = threadIdx.x; i < HWORDS; i += blockDim.x) hist[i] = 0u;
    __syncthreads();

    int wid  = blockIdx.x * (blockDim.x >> 5) + (threadIdx.x >> 5);
    int lane = threadIdx.x & 31;
    unsigned ltmask = (1u << lane) - 1u;
    long start = (long)wid * chunk;
    int iters = chunk >> 5;

    // phase 1: count buckets (ballots only) + smem degree hist
    unsigned myCnt7 = 0;  // lane b<7 accumulates bucket-b count
    for (int it = 0; it < iters; ++it) {
        long idx = start + it * 32 + lane;
        int bkt = 7;
        if (idx < E) {
            int d = __ldcg(&dst[idx]);
            bkt = d / RDIV;
            atomicAdd(&hist[d >> 1], 1u << ((d & 1) * 16));
        }
        #pragma unroll
        for (int b = 0; b < 7; b++) {
            unsigned mb = __ballot_sync(0xFFFFFFFFu, bkt == b);
            if (lane == b) myCnt7 += __popc(mb);
        }
    }

    // one cursor atomic per warp per bucket
    unsigned offReg = 0;
    if (lane < 7 && myCnt7) offReg = atomicAdd(&g_bcur[lane], myCnt7);

    // phase 2: re-stream, write packed words at ballot-ranked positions
    for (int it = 0; it < iters; ++it) {
        long idx = start + it * 32 + lane;
        int bkt = 7;
        unsigned w = 0u;
        if (idx < E) {
            int d = __ldcg(&dst[idx]);
            int s = __ldcg(&src[idx]);
            bkt = d / RDIV;
            w = ((unsigned)(d - bkt * RDIV) << 17) | (unsigned)s;
        }
        unsigned myMask = 0u, myCnt = 0u;
        #pragma unroll
        for (int b = 0; b < 7; b++) {
            unsigned mb = __ballot_sync(0xFFFFFFFFu, bkt == b);
            if (bkt == b) myMask = mb;
            if (lane == b) myCnt = __popc(mb);
        }
        unsigned base = __shfl_sync(0xFFFFFFFFu, offReg, bkt < 7 ? bkt : 0);
        unsigned pos = base + __popc(myMask & ltmask);
        if (idx < E && pos < BCAP) g_bin[bkt * BCAP + pos] = w;
        offReg += myCnt;
    }

    // flush per-block hist unconditionally (coalesced STG, no atomics)
    __syncthreads();
    for (int i = threadIdx.x; i < HWORDS; i += blockDim.x)
        g_dpart[blockIdx.x * HWORDS + i] = hist[i];
}

// ---- node kernels ----

__global__ void k_node1(const float* __restrict__ x) {
    int i = blockIdx.x * blockDim.x + threadIdx.x;  // word index (2 nodes)
    if (i < HWORDS) {
        unsigned sum = 0;  // u16x2 lanes never overflow (deg <= ~110)
        #pragma unroll 4
        for (int b = 0; b < DB_BLOCKS; b++) sum += g_dpart[b * HWORDS + i];
        int n0 = 2 * i, n1 = 2 * i + 1;
        float d0 = rsqrtf(1.0f + (float)(sum & 0xFFFFu));
        float d1 = rsqrtf(1.0f + (float)(sum >> 16));
        g_dinv[n0] = d0; g_dinv[n1] = d1;
        g_pf[n0] = d0 * x[n0]; g_pf[n1] = d1 * x[n1];
    }
}

__global__ void k_node2(const float* __restrict__ W1, const float* __restrict__ b1,
                        const float* __restrict__ W2, int n) {
    int i = blockIdx.x * blockDim.x + threadIdx.x;
    if (i < n) {
        float t = g_pf[i];  // self-loop term
        #pragma unroll
        for (int s = 0; s < SL; s++) t += g_part1[s * NMAX + i];
        float dv = g_dinv[i];
        float sv = dv * t;
        float g0 = 0.0f, g1 = 0.0f;
        #pragma unroll
        for (int j = 0; j < 16; j++) {
            float h = fmaxf(fmaf(sv, __ldg(&W1[j]), __ldg(&b1[j])), 0.0f);
            g0 = fmaf(h, __ldg(&W2[2 * j + 0]), g0);
            g1 = fmaf(h, __ldg(&W2[2 * j + 1]), g1);
        }
        float2 r = make_float2(dv * g0, dv * g1);
        g_rf[i] = r;
        g_rh[i] = __float22half2_rn(r);
    }
}

__global__ void k_out(const float* __restrict__ b2, float* __restrict__ out, int n) {
    int i = blockIdx.x * blockDim.x + threadIdx.x;
    if (i < n) {
        float2 a = g_rf[i];  // self-loop term
        #pragma unroll
        for (int s = 0; s < SL; s++) {
            float2 p = g_part2[s * NMAX + i];
            a.x += p.x; a.y += p.y;
        }
        float dv = g_dinv[i];
        float z0 = fmaf(dv, a.x, __ldg(&b2[0]));
        float z1 = fmaf(dv, a.y, __ldg(&b2[1]));
        float m = fmaxf(z0, z1);
        float lse = m + logf(expf(z0 - m) + expf(z1 - m));
        reinterpret_cast<float2*>(out)[i] = make_float2(z0 - lse, z1 - lse);
    }
}

// ---- layer-1 aggregation: smem p-slice gather + smem tile scatter ----

__global__ void k_agg1(int nmax) {
    extern __shared__ float sm1[];
    float* tile   = sm1;            // RDIV floats
    float* pslice = sm1 + RDIV;     // RDIV floats
    int range = blockIdx.x / SL;
    int slice = blockIdx.x % SL;
    for (int i = threadIdx.x; i < RDIV; i += blockDim.x) tile[i] = 0.0f;

    int count = (int)g_bcur[range];
    if (count > BCAP) count = BCAP;
    const uint32_t* bin = g_bin + range * BCAP;
    int n4 = count >> 2;

    for (int c = 0; c < NR; c++) {
        int slo = c * RDIV;
        int cs = nmax - slo; if (cs > RDIV) cs = RDIV;
        __syncthreads();
        for (int i = threadIdx.x; i < RDIV; i += blockDim.x)
            pslice[i] = (i < cs) ? __ldg(&g_pf[slo + i]) : 0.0f;
        __syncthreads();

        for (int i = slice * (int)blockDim.x + (int)threadIdx.x; i < n4;
             i += SL * (int)blockDim.x) {
            uint4 w = __ldg(reinterpret_cast<const uint4*>(bin) + i);
            int t0 = (int)(w.x & 0x1FFFFu) - slo;
            int t1 = (int)(w.y & 0x1FFFFu) - slo;
            int t2 = (int)(w.z & 0x1FFFFu) - slo;
            int t3 = (int)(w.w & 0x1FFFFu) - slo;
            if ((unsigned)t0 < (unsigned)cs) atomicAdd(&tile[w.x >> 17], pslice[t0]);
            if ((unsigned)t1 < (unsigned)cs) atomicAdd(&tile[w.y >> 17], pslice[t1]);
            if ((unsigned)t2 < (unsigned)cs) atomicAdd(&tile[w.z >> 17], pslice[t2]);
            if ((unsigned)t3 < (unsigned)cs) atomicAdd(&tile[w.w >> 17], pslice[t3]);
        }
        if (slice == 0) {  // <4 tail words
            for (int e = (n4 << 2) + (int)threadIdx.x; e < count; e += blockDim.x) {
                uint32_t w = bin[e];
                int t = (int)(w & 0x1FFFFu) - slo;
                if ((unsigned)t < (unsigned)cs) atomicAdd(&tile[w >> 17], pslice[t]);
            }
        }
    }
    __syncthreads();

    int lo = range * RDIV;
    int rs = nmax - lo; if (rs > RDIV) rs = RDIV;
    for (int i = threadIdx.x; i < rs; i += blockDim.x)
        g_part1[slice * NMAX + lo + i] = tile[i];
}

// ---- layer-2 aggregation: smem half2 r-slice gather + float2 tile scatter ----

__global__ void k_agg2(int nmax) {
    extern __shared__ float sm2[];
    float*   tile2  = sm2;                                   // 2*RDIV floats
    __half2* rslice = reinterpret_cast<__half2*>(sm2 + 2 * RDIV);  // RDIV half2
    int range = blockIdx.x / SL;
    int slice = blockIdx.x % SL;
    for (int i = threadIdx.x; i < 2 * RDIV; i += blockDim.x) tile2[i] = 0.0f;

    int count = (int)g_bcur[range];
    if (count > BCAP) count = BCAP;
    const uint32_t* bin = g_bin + range * BCAP;
    int n4 = count >> 2;

    for (int c = 0; c < NR; c++) {
        int slo = c * RDIV;
        int cs = nmax - slo; if (cs > RDIV) cs = RDIV;
        __syncthreads();
        for (int i = threadIdx.x; i < RDIV; i += blockDim.x)
            rslice[i] = (i < cs) ? __ldg(&g_rh[slo + i]) : __half2(__half(0.f), __half(0.f));
        __syncthreads();

        for (int i = slice * (int)blockDim.x + (int)threadIdx.x; i < n4;
             i += SL * (int)blockDim.x) {
            uint4 w = __ldg(reinterpret_cast<const uint4*>(bin) + i);
            uint32_t ww[4] = {w.x, w.y, w.z, w.w};
            #pragma unroll
            for (int j = 0; j < 4; j++) {
                int t = (int)(ww[j] & 0x1FFFFu) - slo;
                if ((unsigned)t < (unsigned)cs) {
                    float2 r = __half22float2(rslice[t]);
                    int dl = ww[j] >> 17;
                    atomicAdd(&tile2[2 * dl + 0], r.x);
                    atomicAdd(&tile2[2 * dl + 1], r.y);
                }
            }
        }
        if (slice == 0) {  // <4 tail words
            for (int e = (n4 << 2) + (int)threadIdx.x; e < count; e += blockDim.x) {
                uint32_t w = bin[e];
                int t = (int)(w & 0x1FFFFu) - slo;
                if ((unsigned)t < (unsigned)cs) {
                    float2 r = __half22float2(rslice[t]);
                    int dl = w >> 17;
                    atomicAdd(&tile2[2 * dl + 0], r.x);
                    atomicAdd(&tile2[2 * dl + 1], r.y);
                }
            }
        }
    }
    __syncthreads();

    int lo = range * RDIV;
    int rs = nmax - lo; if (rs > RDIV) rs = RDIV;
    for (int i = threadIdx.x; i < rs; i += blockDim.x)
        g_part2[slice * NMAX + lo + i] = make_float2(tile2[2 * i], tile2[2 * i + 1]);
}

// ---------------- launch ----------------

extern "C" void kernel_launch(void* const* d_in, const int* in_sizes, int n_in,
                              void* d_out, int out_size) {
    const float* x  = (const float*)d_in[0];
    const int*   ei = (const int*)  d_in[1];
    const float* W1 = (const float*)d_in[2];
    const float* b1 = (const float*)d_in[3];
    const float* W2 = (const float*)d_in[4];
    const float* b2 = (const float*)d_in[5];
    int n = in_sizes[0];        // 100000
    int E = in_sizes[1] / 2;
    const int* src = ei;
    const int* dst = ei + E;

    const int HIST_BYTES = HWORDS * 4;            // 200 KB
    const int A1_BYTES   = 2 * RDIV * 4;          // ~114 KB
    const int A2_BYTES   = 2 * RDIV * 4 + RDIV * 4;  // ~171 KB
    cudaFuncSetAttribute(k_degbin, cudaFuncAttributeMaxDynamicSharedMemorySize, HIST_BYTES);
    cudaFuncSetAttribute(k_agg1,   cudaFuncAttributeMaxDynamicSharedMemorySize, A1_BYTES);
    cudaFuncSetAttribute(k_agg2,   cudaFuncAttributeMaxDynamicSharedMemorySize, A2_BYTES);

    int chunk = ((E + NWARPS - 1) / NWARPS + 31) & ~31;

    const int TB = 256;
    int nb_w = (HWORDS + TB - 1) / TB;
    int nb_n = (n + TB - 1) / TB;

    k_init  <<<1, 32>>>();
    k_degbin<<<DB_BLOCKS, DB_TPB, HIST_BYTES>>>(src, dst, E, chunk);
    k_node1 <<<nb_w, TB>>>(x);
    k_agg1  <<<NR * SL, 1024, A1_BYTES>>>(n);
    k_node2 <<<nb_n, TB>>>(W1, b1, W2, n);
    k_agg2  <<<NR * SL, 1024, A2_BYTES>>>(n);
    k_out   <<<nb_n, TB>>>(b2, (float*)d_out, n);
}

// round 11
// speedup vs baseline: 1.0495x; 1.0495x over previous
#include <cuda_runtime.h>
#include <cstdint>

#define NMAX   100000
#define HWORDS 50000           // packed uint16x2 degree words
#define RDIV   14286           // nodes per dst-range (7*14286 >= 100000)
#define NR     7
#define SL     21              // slices per range: 7*21 = 147 agg blocks
#define BCAP   1000000         // per-bucket capacity (true ~914K)

// Scratch (device globals; no allocation allowed)
__device__ uint32_t g_degpack[HWORDS];
__device__ uint32_t g_bcur[8];
__device__ __align__(16) uint32_t g_bin[NR * BCAP];   // packed (dl<<17)|src
__device__ float    g_dinv[NMAX];
__device__ __align__(16) float  g_pf[NMAX];           // layer-1 node values
__device__ __align__(16) float2 g_rf[NMAX];           // layer-2 node values
__device__ __align__(16) float  g_part1[SL * NMAX];   // agg1 slice partials
__device__ __align__(16) float2 g_part2[SL * NMAX];   // agg2 slice partials

// ---------------- init ----------------

__global__ void k_init() {
    int i = blockIdx.x * blockDim.x + threadIdx.x;
    if (i < HWORDS) g_degpack[i] = 0u;
    if (i < 8) g_bcur[i] = 0u;
}

// -------- degree: smem-privatized packed histogram (proven ~11us) ----

__global__ void k_deg(const int* __restrict__ dst, int E) {
    extern __shared__ uint32_t hist[];  // HWORDS words = 200KB
    for (int i = threadIdx.x; i < HWORDS; i += blockDim.x) hist[i] = 0u;
    __syncthreads();

    int e8 = E >> 3;
    int stride = gridDim.x * blockDim.x;
    for (int i = blockIdx.x * blockDim.x + threadIdx.x; i < e8; i += stride) {
        int4 a = __ldcg(reinterpret_cast<const int4*>(dst) + 2 * i);
        int4 b = __ldcg(reinterpret_cast<const int4*>(dst) + 2 * i + 1);
        atomicAdd(&hist[a.x >> 1], 1u << ((a.x & 1) * 16));
        atomicAdd(&hist[a.y >> 1], 1u << ((a.y & 1) * 16));
        atomicAdd(&hist[a.z >> 1], 1u << ((a.z & 1) * 16));
        atomicAdd(&hist[a.w >> 1], 1u << ((a.w & 1) * 16));
        atomicAdd(&hist[b.x >> 1], 1u << ((b.x & 1) * 16));
        atomicAdd(&hist[b.y >> 1], 1u << ((b.y & 1) * 16));
        atomicAdd(&hist[b.z >> 1], 1u << ((b.z & 1) * 16));
        atomicAdd(&hist[b.w >> 1], 1u << ((b.w & 1) * 16));
    }
    if (blockIdx.x == 0) {  // tail
        for (int e = (e8 << 3) + (int)threadIdx.x; e < E; e += blockDim.x) {
            int d = dst[e];
            atomicAdd(&hist[d >> 1], 1u << ((d & 1) * 16));
        }
    }
    __syncthreads();

    for (int i = threadIdx.x; i < HWORDS; i += blockDim.x) {
        uint32_t v = hist[i];
        if (v) atomicAdd(&g_degpack[i], v);
    }
}

// -------- binning: match_any warp-aggregated dst-range partition --------

__global__ void k_bin(const int* __restrict__ src, const int* __restrict__ dst, int E) {
    int lane = threadIdx.x & 31;
    unsigned ltmask = (1u << lane) - 1u;
    int stride = gridDim.x * blockDim.x;
    int Epad = (E + 31) & ~31;  // keep warps converged

    for (int i = blockIdx.x * blockDim.x + threadIdx.x; i < Epad; i += stride) {
        int bkt = 7;
        unsigned w = 0u;
        if (i < E) {
            int d = __ldcg(&dst[i]);
            int s = __ldcg(&src[i]);
            bkt = d / RDIV;              // 0..6 (mul-high)
            w = ((unsigned)(d - bkt * RDIV) << 17) | (unsigned)s;
        }
        unsigned m = __match_any_sync(0xFFFFFFFFu, bkt);
        int leader = __ffs(m) - 1;
        unsigned rank = __popc(m & ltmask);
        unsigned base = 0u;
        if (lane == leader) base = atomicAdd(&g_bcur[bkt], __popc(m));
        base = __shfl_sync(0xFFFFFFFFu, base, leader);
        if (bkt < 7) {
            unsigned pos = base + rank;
            if (pos < BCAP) g_bin[bkt * BCAP + pos] = w;
        }
    }
}

// ---------------- node kernels ----------------

__global__ void k_node1(const float* __restrict__ x, int n) {
    int i = blockIdx.x * blockDim.x + threadIdx.x;
    if (i < n) {
        uint32_t pack = g_degpack[i >> 1];
        uint32_t cnt = (pack >> ((i & 1) * 16)) & 0xFFFFu;
        float d = rsqrtf(1.0f + (float)cnt);   // +1 = self-loop
        g_dinv[i] = d;
        g_pf[i] = d * x[i];
    }
}

__global__ void k_node2(const float* __restrict__ W1, const float* __restrict__ b1,
                        const float* __restrict__ W2, int n) {
    int i = blockIdx.x * blockDim.x + threadIdx.x;
    if (i < n) {
        float t = g_pf[i];  // self-loop term
        #pragma unroll
        for (int s = 0; s < SL; s++) t += g_part1[s * NMAX + i];
        float dv = g_dinv[i];
        float sv = dv * t;
        float g0 = 0.0f, g1 = 0.0f;
        #pragma unroll
        for (int j = 0; j < 16; j++) {
            float h = fmaxf(fmaf(sv, __ldg(&W1[j]), __ldg(&b1[j])), 0.0f);
            g0 = fmaf(h, __ldg(&W2[2 * j + 0]), g0);
            g1 = fmaf(h, __ldg(&W2[2 * j + 1]), g1);
        }
        g_rf[i] = make_float2(dv * g0, dv * g1);
    }
}

__global__ void k_out(const float* __restrict__ b2, float* __restrict__ out, int n) {
    int i = blockIdx.x * blockDim.x + threadIdx.x;
    if (i < n) {
        float2 a = g_rf[i];  // self-loop term
        #pragma unroll
        for (int s = 0; s < SL; s++) {
            float2 p = g_part2[s * NMAX + i];
            a.x += p.x; a.y += p.y;
        }
        float dv = g_dinv[i];
        float z0 = fmaf(dv, a.x, __ldg(&b2[0]));
        float z1 = fmaf(dv, a.y, __ldg(&b2[1]));
        float m = fmaxf(z0, z1);
        float lse = m + logf(expf(z0 - m) + expf(z1 - m));
        reinterpret_cast<float2*>(out)[i] = make_float2(z0 - lse, z1 - lse);
    }
}

// ---- layer-1 aggregation: coalesced bin read + 1 random gather + smem tile ----

__global__ void k_agg1(int nmax) {
    extern __shared__ float tile[];  // RDIV floats = ~57KB
    int range = blockIdx.x / SL;
    int slice = blockIdx.x % SL;
    for (int i = threadIdx.x; i < RDIV; i += blockDim.x) tile[i] = 0.0f;
    __syncthreads();

    int count = (int)g_bcur[range];
    if (count > BCAP) count = BCAP;
    const uint32_t* bin = g_bin + range * BCAP;
    int n4 = count >> 2;
    for (int i = slice * (int)blockDim.x + (int)threadIdx.x; i < n4;
         i += SL * (int)blockDim.x) {
        uint4 w = __ldg(reinterpret_cast<const uint4*>(bin) + i);
        float p0 = __ldg(&g_pf[w.x & 0x1FFFFu]);   // 4 batched random gathers
        float p1 = __ldg(&g_pf[w.y & 0x1FFFFu]);
        float p2 = __ldg(&g_pf[w.z & 0x1FFFFu]);
        float p3 = __ldg(&g_pf[w.w & 0x1FFFFu]);
        atomicAdd(&tile[w.x >> 17], p0);
        atomicAdd(&tile[w.y >> 17], p1);
        atomicAdd(&tile[w.z >> 17], p2);
        atomicAdd(&tile[w.w >> 17], p3);
    }
    if (slice == 0) {  // <4 tail words
        for (int e = (n4 << 2) + (int)threadIdx.x; e < count; e += blockDim.x) {
            uint32_t w = bin[e];
            atomicAdd(&tile[w >> 17], __ldg(&g_pf[w & 0x1FFFFu]));
        }
    }
    __syncthreads();

    int lo = range * RDIV;
    int rs = nmax - lo; if (rs > RDIV) rs = RDIV;
    for (int i = threadIdx.x; i < rs; i += blockDim.x)
        g_part1[slice * NMAX + lo + i] = tile[i];  // coalesced STG
}

// ---- layer-2 aggregation: float2 gathers + float2 smem tile ----

__global__ void k_agg2(int nmax) {
    extern __shared__ float tile2[];  // 2*RDIV floats = ~114KB
    int range = blockIdx.x / SL;
    int slice = blockIdx.x % SL;
    for (int i = threadIdx.x; i < 2 * RDIV; i += blockDim.x) tile2[i] = 0.0f;
    __syncthreads();

    int count = (int)g_bcur[range];
    if (count > BCAP) count = BCAP;
    const uint32_t* bin = g_bin + range * BCAP;
    int n4 = count >> 2;
    for (int i = slice * (int)blockDim.x + (int)threadIdx.x; i < n4;
         i += SL * (int)blockDim.x) {
        uint4 w = __ldg(reinterpret_cast<const uint4*>(bin) + i);
        float2 r0 = __ldg(&g_rf[w.x & 0x1FFFFu]);  // 4 batched random gathers
        float2 r1 = __ldg(&g_rf[w.y & 0x1FFFFu]);
        float2 r2 = __ldg(&g_rf[w.z & 0x1FFFFu]);
        float2 r3 = __ldg(&g_rf[w.w & 0x1FFFFu]);
        atomicAdd(&tile2[2 * (w.x >> 17) + 0], r0.x);
        atomicAdd(&tile2[2 * (w.x >> 17) + 1], r0.y);
        atomicAdd(&tile2[2 * (w.y >> 17) + 0], r1.x);
        atomicAdd(&tile2[2 * (w.y >> 17) + 1], r1.y);
        atomicAdd(&tile2[2 * (w.z >> 17) + 0], r2.x);
        atomicAdd(&tile2[2 * (w.z >> 17) + 1], r2.y);
        atomicAdd(&tile2[2 * (w.w >> 17) + 0], r3.x);
        atomicAdd(&tile2[2 * (w.w >> 17) + 1], r3.y);
    }
    if (slice == 0) {  // <4 tail words
        for (int e = (n4 << 2) + (int)threadIdx.x; e < count; e += blockDim.x) {
            uint32_t w = bin[e];
            float2 r = __ldg(&g_rf[w & 0x1FFFFu]);
            atomicAdd(&tile2[2 * (w >> 17) + 0], r.x);
            atomicAdd(&tile2[2 * (w >> 17) + 1], r.y);
        }
    }
    __syncthreads();

    int lo = range * RDIV;
    int rs = nmax - lo; if (rs > RDIV) rs = RDIV;
    for (int i = threadIdx.x; i < rs; i += blockDim.x)
        g_part2[slice * NMAX + lo + i] = make_float2(tile2[2 * i], tile2[2 * i + 1]);
}

// ---------------- launch ----------------

extern "C" void kernel_launch(void* const* d_in, const int* in_sizes, int n_in,
                              void* d_out, int out_size) {
    const float* x  = (const float*)d_in[0];
    const int*   ei = (const int*)  d_in[1];
    const float* W1 = (const float*)d_in[2];
    const float* b1 = (const float*)d_in[3];
    const float* W2 = (const float*)d_in[4];
    const float* b2 = (const float*)d_in[5];
    int n = in_sizes[0];        // 100000
    int E = in_sizes[1] / 2;
    const int* src = ei;
    const int* dst = ei + E;

    const int HIST_BYTES = HWORDS * 4;   // 200 KB
    const int A1_BYTES   = RDIV * 4;     // ~57 KB
    const int A2_BYTES   = RDIV * 8;     // ~114 KB
    cudaFuncSetAttribute(k_deg,  cudaFuncAttributeMaxDynamicSharedMemorySize, HIST_BYTES);
    cudaFuncSetAttribute(k_agg1, cudaFuncAttributeMaxDynamicSharedMemorySize, A1_BYTES);
    cudaFuncSetAttribute(k_agg2, cudaFuncAttributeMaxDynamicSharedMemorySize, A2_BYTES);

    const int TB = 256;
    int nb_n = (n + TB - 1) / TB;
    int nb_h = (HWORDS + TB - 1) / TB;

    k_init <<<nb_h, TB>>>();
    k_deg  <<<148, 1024, HIST_BYTES>>>(dst, E);
    k_bin  <<<592, 256>>>(src, dst, E);
    k_node1<<<nb_n, TB>>>(x, n);
    k_agg1 <<<NR * SL, 1024, A1_BYTES>>>(n);
    k_node2<<<nb_n, TB>>>(W1, b1, W2, n);
    k_agg2 <<<NR * SL, 1024, A2_BYTES>>>(n);
    k_out  <<<nb_n, TB>>>(b2, (float*)d_out, n);
}

// round 12
// speedup vs baseline: 1.5258x; 1.4539x over previous
#include <cuda_runtime.h>
#include <cstdint>

#define NMAX   100000
#define HWORDS 50000           // packed uint16x2 degree words
#define RDIV   14286           // nodes per dst-range (7*14286 = 100002)
#define NR     7
#define SL     21              // slices per range: 7*21 = 147 agg blocks
#define BCAP   940000          // per-bucket capacity (true ~914K +- 1K)
#define CB     148             // count/scatter blocks
#define CT     1024            // count/scatter threads
#define NW     (CB * (CT / 32))  // 4736 warps

// Scratch (device globals; no allocation allowed)
__device__ uint32_t g_degpack[HWORDS];
__device__ uint32_t g_wcnt[NR * NW];    // per-bucket per-warp counts
__device__ uint32_t g_wbase[NR * NW];   // exclusive bases within bucket
__device__ uint32_t g_btot[NR];         // bucket totals
__device__ __align__(16) uint32_t g_bin[NR * BCAP];  // packed (dl<<17)|src
__device__ float    g_dinv[NMAX];
__device__ __align__(16) float  g_pf[NMAX];          // layer-1 node values
__device__ __align__(16) float2 g_rf[NMAX];          // layer-2 node values
__device__ __align__(16) float  g_part1[SL * NMAX];  // agg1 slice partials
__device__ __align__(16) float2 g_part2[SL * NMAX];  // agg2 slice partials

// ---------------- init ----------------

__global__ void k_init() {
    int i = blockIdx.x * blockDim.x + threadIdx.x;
    if (i < HWORDS) g_degpack[i] = 0u;
}

// ---- pass 1: degree smem histogram + per-warp bucket counts (ballots) ----

__global__ void k_degcount(const int* __restrict__ dst, int E, int chunk) {
    extern __shared__ uint32_t hist[];  // HWORDS = 200KB
    for (int i = threadIdx.x; i < HWORDS; i += blockDim.x) hist[i] = 0u;
    __syncthreads();

    int wid  = blockIdx.x * (blockDim.x >> 5) + (threadIdx.x >> 5);
    int lane = threadIdx.x & 31;
    long start = (long)wid * chunk;
    int iters = chunk >> 5;

    unsigned myCnt = 0;  // lane b<7 accumulates bucket-b count
    for (int it = 0; it < iters; ++it) {
        long idx = start + it * 32 + lane;
        int bkt = 7;
        if (idx < E) {
            int d = __ldcg(&dst[idx]);
            bkt = d / RDIV;
            atomicAdd(&hist[d >> 1], 1u << ((d & 1) * 16));
        }
        #pragma unroll
        for (int b = 0; b < 7; b++) {
            unsigned mb = __ballot_sync(0xFFFFFFFFu, bkt == b);
            if (lane == b) myCnt += __popc(mb);
        }
    }
    if (lane < 7) g_wcnt[lane * NW + wid] = myCnt;

    __syncthreads();
    for (int i = threadIdx.x; i < HWORDS; i += blockDim.x) {
        uint32_t v = hist[i];
        if (v) atomicAdd(&g_degpack[i], v);
    }
}

// ---- pass 2: exclusive scan of per-warp counts (7 blocks, one per bucket) ----

#define SCHUNK 5  // ceil(4736/1024)

__global__ void k_scan() {
    __shared__ uint32_t ssum[1024];
    int b = blockIdx.x;
    int t = threadIdx.x;
    const uint32_t* cnt = g_wcnt + b * NW;
    uint32_t* base = g_wbase + b * NW;

    uint32_t v[SCHUNK];
    uint32_t s = 0;
    int i0 = t * SCHUNK;
    #pragma unroll
    for (int k = 0; k < SCHUNK; k++) {
        int i = i0 + k;
        v[k] = (i < NW) ? cnt[i] : 0u;
        s += v[k];
    }
    ssum[t] = s;
    __syncthreads();
    for (int off = 1; off < 1024; off <<= 1) {
        uint32_t add = (t >= off) ? ssum[t - off] : 0u;
        __syncthreads();
        ssum[t] += add;
        __syncthreads();
    }
    uint32_t excl = ssum[t] - s;
    #pragma unroll
    for (int k = 0; k < SCHUNK; k++) {
        int i = i0 + k;
        if (i < NW) { base[i] = excl; excl += v[k]; }
    }
    if (t == 1023) g_btot[b] = ssum[1023];
}

// ---- pass 3: scatter packed words at ballot-ranked positions (no atomics) ----

__global__ void k_scatter(const int* __restrict__ src, const int* __restrict__ dst,
                          int E, int chunk) {
    int wid  = blockIdx.x * (blockDim.x >> 5) + (threadIdx.x >> 5);
    int lane = threadIdx.x & 31;
    unsigned ltmask = (1u << lane) - 1u;
    long start = (long)wid * chunk;
    int iters = chunk >> 5;

    unsigned offReg = (lane < 7) ? g_wbase[lane * NW + wid] : 0u;

    for (int it = 0; it < iters; ++it) {
        long idx = start + it * 32 + lane;
        int bkt = 7;
        unsigned w = 0u;
        if (idx < E) {
            int d = __ldcg(&dst[idx]);
            int s = __ldcg(&src[idx]);
            bkt = d / RDIV;
            w = ((unsigned)(d - bkt * RDIV) << 17) | (unsigned)s;
        }
        unsigned myMask = 0u, myCnt = 0u;
        #pragma unroll
        for (int b = 0; b < 7; b++) {
            unsigned mb = __ballot_sync(0xFFFFFFFFu, bkt == b);
            if (bkt == b) myMask = mb;
            if (lane == b) myCnt = __popc(mb);
        }
        unsigned base = __shfl_sync(0xFFFFFFFFu, offReg, bkt < 7 ? bkt : 0);
        if (bkt < 7) {
            unsigned pos = base + __popc(myMask & ltmask);
            if (pos < BCAP) g_bin[bkt * BCAP + pos] = w;
        }
        offReg += myCnt;
    }
}

// ---------------- node kernels ----------------

__global__ void k_node1(const float* __restrict__ x, int n) {
    int i = blockIdx.x * blockDim.x + threadIdx.x;
    if (i < n) {
        uint32_t pack = g_degpack[i >> 1];
        uint32_t cnt = (pack >> ((i & 1) * 16)) & 0xFFFFu;
        float d = rsqrtf(1.0f + (float)cnt);   // +1 = self-loop
        g_dinv[i] = d;
        g_pf[i] = d * x[i];
    }
}

__global__ void k_node2(const float* __restrict__ W1, const float* __restrict__ b1,
                        const float* __restrict__ W2, int n) {
    int i = blockIdx.x * blockDim.x + threadIdx.x;
    if (i < n) {
        float t = g_pf[i];  // self-loop term
        #pragma unroll
        for (int s = 0; s < SL; s++) t += g_part1[s * NMAX + i];
        float dv = g_dinv[i];
        float sv = dv * t;
        float g0 = 0.0f, g1 = 0.0f;
        #pragma unroll
        for (int j = 0; j < 16; j++) {
            float h = fmaxf(fmaf(sv, __ldg(&W1[j]), __ldg(&b1[j])), 0.0f);
            g0 = fmaf(h, __ldg(&W2[2 * j + 0]), g0);
            g1 = fmaf(h, __ldg(&W2[2 * j + 1]), g1);
        }
        g_rf[i] = make_float2(dv * g0, dv * g1);
    }
}

__global__ void k_out(const float* __restrict__ b2, float* __restrict__ out, int n) {
    int i = blockIdx.x * blockDim.x + threadIdx.x;
    if (i < n) {
        float2 a = g_rf[i];  // self-loop term
        #pragma unroll
        for (int s = 0; s < SL; s++) {
            float2 p = g_part2[s * NMAX + i];
            a.x += p.x; a.y += p.y;
        }
        float dv = g_dinv[i];
        float z0 = fmaf(dv, a.x, __ldg(&b2[0]));
        float z1 = fmaf(dv, a.y, __ldg(&b2[1]));
        float m = fmaxf(z0, z1);
        float lse = m + logf(expf(z0 - m) + expf(z1 - m));
        reinterpret_cast<float2*>(out)[i] = make_float2(z0 - lse, z1 - lse);
    }
}

// ---- layer-1 aggregation: coalesced bin read + 1 random gather + smem tile ----

__global__ void k_agg1(int nmax) {
    extern __shared__ float tile[];  // RDIV floats = ~57KB
    int range = blockIdx.x / SL;
    int slice = blockIdx.x % SL;
    for (int i = threadIdx.x; i < RDIV; i += blockDim.x) tile[i] = 0.0f;
    __syncthreads();

    int count = (int)g_btot[range];
    if (count > BCAP) count = BCAP;
    const uint32_t* bin = g_bin + range * BCAP;
    int n4 = count >> 2;
    for (int i = slice * (int)blockDim.x + (int)threadIdx.x; i < n4;
         i += SL * (int)blockDim.x) {
        uint4 w = __ldg(reinterpret_cast<const uint4*>(bin) + i);
        float p0 = __ldg(&g_pf[w.x & 0x1FFFFu]);   // 4 batched random gathers
        float p1 = __ldg(&g_pf[w.y & 0x1FFFFu]);
        float p2 = __ldg(&g_pf[w.z & 0x1FFFFu]);
        float p3 = __ldg(&g_pf[w.w & 0x1FFFFu]);
        atomicAdd(&tile[w.x >> 17], p0);
        atomicAdd(&tile[w.y >> 17], p1);
        atomicAdd(&tile[w.z >> 17], p2);
        atomicAdd(&tile[w.w >> 17], p3);
    }
    if (slice == 0) {  // <4 tail words
        for (int e = (n4 << 2) + (int)threadIdx.x; e < count; e += blockDim.x) {
            uint32_t w = bin[e];
            atomicAdd(&tile[w >> 17], __ldg(&g_pf[w & 0x1FFFFu]));
        }
    }
    __syncthreads();

    int lo = range * RDIV;
    int rs = nmax - lo; if (rs > RDIV) rs = RDIV;
    for (int i = threadIdx.x; i < rs; i += blockDim.x)
        g_part1[slice * NMAX + lo + i] = tile[i];  // coalesced STG
}

// ---- layer-2 aggregation: float2 gathers + float2 smem tile ----

__global__ void k_agg2(int nmax) {
    extern __shared__ float tile2[];  // 2*RDIV floats = ~114KB
    int range = blockIdx.x / SL;
    int slice = blockIdx.x % SL;
    for (int i = threadIdx.x; i < 2 * RDIV; i += blockDim.x) tile2[i] = 0.0f;
    __syncthreads();

    int count = (int)g_btot[range];
    if (count > BCAP) count = BCAP;
    const uint32_t* bin = g_bin + range * BCAP;
    int n4 = count >> 2;
    for (int i = slice * (int)blockDim.x + (int)threadIdx.x; i < n4;
         i += SL * (int)blockDim.x) {
        uint4 w = __ldg(reinterpret_cast<const uint4*>(bin) + i);
        float2 r0 = __ldg(&g_rf[w.x & 0x1FFFFu]);  // 4 batched random gathers
        float2 r1 = __ldg(&g_rf[w.y & 0x1FFFFu]);
        float2 r2 = __ldg(&g_rf[w.z & 0x1FFFFu]);
        float2 r3 = __ldg(&g_rf[w.w & 0x1FFFFu]);
        atomicAdd(&tile2[2 * (w.x >> 17) + 0], r0.x);
        atomicAdd(&tile2[2 * (w.x >> 17) + 1], r0.y);
        atomicAdd(&tile2[2 * (w.y >> 17) + 0], r1.x);
        atomicAdd(&tile2[2 * (w.y >> 17) + 1], r1.y);
        atomicAdd(&tile2[2 * (w.z >> 17) + 0], r2.x);
        atomicAdd(&tile2[2 * (w.z >> 17) + 1], r2.y);
        atomicAdd(&tile2[2 * (w.w >> 17) + 0], r3.x);
        atomicAdd(&tile2[2 * (w.w >> 17) + 1], r3.y);
    }
    if (slice == 0) {  // <4 tail words
        for (int e = (n4 << 2) + (int)threadIdx.x; e < count; e += blockDim.x) {
            uint32_t w = bin[e];
            float2 r = __ldg(&g_rf[w & 0x1FFFFu]);
            atomicAdd(&tile2[2 * (w >> 17) + 0], r.x);
            atomicAdd(&tile2[2 * (w >> 17) + 1], r.y);
        }
    }
    __syncthreads();

    int lo = range * RDIV;
    int rs = nmax - lo; if (rs > RDIV) rs = RDIV;
    for (int i = threadIdx.x; i < rs; i += blockDim.x)
        g_part2[slice * NMAX + lo + i] = make_float2(tile2[2 * i], tile2[2 * i + 1]);
}

// ---------------- launch ----------------

extern "C" void kernel_launch(void* const* d_in, const int* in_sizes, int n_in,
                              void* d_out, int out_size) {
    const float* x  = (const float*)d_in[0];
    const int*   ei = (const int*)  d_in[1];
    const float* W1 = (const float*)d_in[2];
    const float* b1 = (const float*)d_in[3];
    const float* W2 = (const float*)d_in[4];
    const float* b2 = (const float*)d_in[5];
    int n = in_sizes[0];        // 100000
    int E = in_sizes[1] / 2;
    const int* src = ei;
    const int* dst = ei + E;

    const int HIST_BYTES = HWORDS * 4;   // 200 KB
    const int A1_BYTES   = RDIV * 4;     // ~57 KB
    const int A2_BYTES   = RDIV * 8;     // ~114 KB
    cudaFuncSetAttribute(k_degcount, cudaFuncAttributeMaxDynamicSharedMemorySize, HIST_BYTES);
    cudaFuncSetAttribute(k_agg1, cudaFuncAttributeMaxDynamicSharedMemorySize, A1_BYTES);
    cudaFuncSetAttribute(k_agg2, cudaFuncAttributeMaxDynamicSharedMemorySize, A2_BYTES);

    int chunk = (((E + NW - 1) / NW) + 31) & ~31;

    const int TB = 256;
    int nb_n = (n + TB - 1) / TB;
    int nb_h = (HWORDS + TB - 1) / TB;

    k_init    <<<nb_h, TB>>>();
    k_degcount<<<CB, CT, HIST_BYTES>>>(dst, E, chunk);
    k_scan    <<<NR, 1024>>>();
    k_scatter <<<CB, CT>>>(src, dst, E, chunk);
    k_node1   <<<nb_n, TB>>>(x, n);
    k_agg1    <<<NR * SL, 1024, A1_BYTES>>>(n);
    k_node2   <<<nb_n, TB>>>(W1, b1, W2, n);
    k_agg2    <<<NR * SL, 1024, A2_BYTES>>>(n);
    k_out     <<<nb_n, TB>>>(b2, (float*)d_out, n);
}

// round 13
// speedup vs baseline: 2.0344x; 1.3333x over previous
#include <cuda_runtime.h>
#include <cstdint>

#define NMAX   100000
#define HWORDS 50000   // packed uint16x2 degree words

// Scratch (device globals; no allocation allowed)
__device__ uint32_t g_degpack[HWORDS];           // zeroed by k_node1 after use
__device__ float    g_dinv[NMAX];
__device__ __align__(16) float  g_pf[NMAX];      // layer-1 gather array
__device__ float    g_t[NMAX];                   // layer-1 accumulator (init=self-loop)
__device__ __align__(16) float2 g_rf[NMAX];      // layer-2 gather array
__device__ float2   g_acc[NMAX];                 // layer-2 accumulator (init=self-loop)

__device__ __forceinline__ void red_add_f32(float* addr, float v) {
    asm volatile("red.global.add.f32 [%0], %1;" :: "l"(addr), "f"(v) : "memory");
}
__device__ __forceinline__ void red_add_v2(float2* addr, float x, float y) {
    asm volatile("red.global.add.v2.f32 [%0], {%1, %2};"
                 :: "l"(addr), "f"(x), "f"(y) : "memory");
}

// -------- degree: smem-privatized packed histogram (measured ~11us) --------

__global__ void k_deg(const int* __restrict__ dst, int E) {
    extern __shared__ uint32_t hist[];  // HWORDS words = 200KB
    for (int i = threadIdx.x; i < HWORDS; i += blockDim.x) hist[i] = 0u;
    __syncthreads();

    int e8 = E >> 3;
    int stride = gridDim.x * blockDim.x;
    for (int i = blockIdx.x * blockDim.x + threadIdx.x; i < e8; i += stride) {
        int4 a = __ldcg(reinterpret_cast<const int4*>(dst) + 2 * i);
        int4 b = __ldcg(reinterpret_cast<const int4*>(dst) + 2 * i + 1);
        atomicAdd(&hist[a.x >> 1], 1u << ((a.x & 1) * 16));
        atomicAdd(&hist[a.y >> 1], 1u << ((a.y & 1) * 16));
        atomicAdd(&hist[a.z >> 1], 1u << ((a.z & 1) * 16));
        atomicAdd(&hist[a.w >> 1], 1u << ((a.w & 1) * 16));
        atomicAdd(&hist[b.x >> 1], 1u << ((b.x & 1) * 16));
        atomicAdd(&hist[b.y >> 1], 1u << ((b.y & 1) * 16));
        atomicAdd(&hist[b.z >> 1], 1u << ((b.z & 1) * 16));
        atomicAdd(&hist[b.w >> 1], 1u << ((b.w & 1) * 16));
    }
    if (blockIdx.x == 0) {  // tail (E % 8)
        for (int e = (e8 << 3) + (int)threadIdx.x; e < E; e += blockDim.x) {
            int d = dst[e];
            atomicAdd(&hist[d >> 1], 1u << ((d & 1) * 16));
        }
    }
    __syncthreads();

    for (int i = threadIdx.x; i < HWORDS; i += blockDim.x) {
        uint32_t v = hist[i];
        if (v) atomicAdd(&g_degpack[i], v);
    }
}

// ---- node1: one thread per degpack WORD (2 nodes); zero word for next replay ----

__global__ void k_node1(const float* __restrict__ x) {
    int stride = gridDim.x * blockDim.x;
    for (int i = blockIdx.x * blockDim.x + threadIdx.x; i < HWORDS; i += stride) {
        uint32_t pack = g_degpack[i];
        g_degpack[i] = 0u;                 // ready for next graph replay
        int n0 = 2 * i, n1 = 2 * i + 1;
        float d0 = rsqrtf(1.0f + (float)(pack & 0xFFFFu));   // +1 = self-loop
        float d1 = rsqrtf(1.0f + (float)(pack >> 16));
        float p0 = d0 * x[n0];
        float p1 = d1 * x[n1];
        g_dinv[n0] = d0; g_dinv[n1] = d1;
        g_pf[n0] = p0;   g_pf[n1] = p1;
        g_t[n0] = p0;    g_t[n1] = p1;     // self-loop term
    }
}

// ---- layer-1 aggregation: 8 edges/thread, 1 gather + 1 RED per edge ----

__global__ void k_agg1(const int* __restrict__ src, const int* __restrict__ dst, int E) {
    int i = blockIdx.x * blockDim.x + threadIdx.x;
    int base = i * 8;
    if (base + 7 < E) {
        int4 sa = __ldcg(reinterpret_cast<const int4*>(src) + 2 * i);
        int4 sb = __ldcg(reinterpret_cast<const int4*>(src) + 2 * i + 1);
        int4 da = __ldcg(reinterpret_cast<const int4*>(dst) + 2 * i);
        int4 db = __ldcg(reinterpret_cast<const int4*>(dst) + 2 * i + 1);
        float p0 = __ldg(&g_pf[sa.x]);
        float p1 = __ldg(&g_pf[sa.y]);
        float p2 = __ldg(&g_pf[sa.z]);
        float p3 = __ldg(&g_pf[sa.w]);
        float p4 = __ldg(&g_pf[sb.x]);
        float p5 = __ldg(&g_pf[sb.y]);
        float p6 = __ldg(&g_pf[sb.z]);
        float p7 = __ldg(&g_pf[sb.w]);
        red_add_f32(&g_t[da.x], p0);
        red_add_f32(&g_t[da.y], p1);
        red_add_f32(&g_t[da.z], p2);
        red_add_f32(&g_t[da.w], p3);
        red_add_f32(&g_t[db.x], p4);
        red_add_f32(&g_t[db.y], p5);
        red_add_f32(&g_t[db.z], p6);
        red_add_f32(&g_t[db.w], p7);
    } else if (base < E) {
        for (int e = base; e < E; ++e)
            red_add_f32(&g_t[dst[e]], __ldg(&g_pf[src[e]]));
    }
}

// ---- node2: layer-1 normalize + 16-wide MLP + layer-2 message precompute ----

__global__ void k_node2(const float* __restrict__ W1, const float* __restrict__ b1,
                        const float* __restrict__ W2, int n) {
    int stride = gridDim.x * blockDim.x;
    for (int i = blockIdx.x * blockDim.x + threadIdx.x; i < n; i += stride) {
        float dv = g_dinv[i];
        float sv = dv * g_t[i];  // layer-1 aggregated scalar
        float g0 = 0.0f, g1 = 0.0f;
        #pragma unroll
        for (int j = 0; j < 16; j++) {
            float h = fmaxf(fmaf(sv, __ldg(&W1[j]), __ldg(&b1[j])), 0.0f);
            g0 = fmaf(h, __ldg(&W2[2 * j + 0]), g0);
            g1 = fmaf(h, __ldg(&W2[2 * j + 1]), g1);
        }
        float2 r = make_float2(dv * g0, dv * g1);
        g_rf[i] = r;
        g_acc[i] = r;  // self-loop term
    }
}

// ---- layer-2 aggregation: float2 gather + vector RED per edge ----

__global__ void k_agg2(const int* __restrict__ src, const int* __restrict__ dst, int E) {
    int i = blockIdx.x * blockDim.x + threadIdx.x;
    int base = i * 8;
    if (base + 7 < E) {
        int4 sa = __ldcg(reinterpret_cast<const int4*>(src) + 2 * i);
        int4 sb = __ldcg(reinterpret_cast<const int4*>(src) + 2 * i + 1);
        int4 da = __ldcg(reinterpret_cast<const int4*>(dst) + 2 * i);
        int4 db = __ldcg(reinterpret_cast<const int4*>(dst) + 2 * i + 1);
        float2 r0 = __ldg(&g_rf[sa.x]);
        float2 r1 = __ldg(&g_rf[sa.y]);
        float2 r2 = __ldg(&g_rf[sa.z]);
        float2 r3 = __ldg(&g_rf[sa.w]);
        float2 r4 = __ldg(&g_rf[sb.x]);
        float2 r5 = __ldg(&g_rf[sb.y]);
        float2 r6 = __ldg(&g_rf[sb.z]);
        float2 r7 = __ldg(&g_rf[sb.w]);
        red_add_v2(&g_acc[da.x], r0.x, r0.y);
        red_add_v2(&g_acc[da.y], r1.x, r1.y);
        red_add_v2(&g_acc[da.z], r2.x, r2.y);
        red_add_v2(&g_acc[da.w], r3.x, r3.y);
        red_add_v2(&g_acc[db.x], r4.x, r4.y);
        red_add_v2(&g_acc[db.y], r5.x, r5.y);
        red_add_v2(&g_acc[db.z], r6.x, r6.y);
        red_add_v2(&g_acc[db.w], r7.x, r7.y);
    } else if (base < E) {
        for (int e = base; e < E; ++e) {
            float2 r = __ldg(&g_rf[src[e]]);
            red_add_v2(&g_acc[dst[e]], r.x, r.y);
        }
    }
}

// ---- output: layer-2 normalize + 2-class log_softmax ----

__global__ void k_out(const float* __restrict__ b2, float* __restrict__ out, int n) {
    int stride = gridDim.x * blockDim.x;
    for (int i = blockIdx.x * blockDim.x + threadIdx.x; i < n; i += stride) {
        float dv = g_dinv[i];
        float2 a = g_acc[i];
        float z0 = fmaf(dv, a.x, __ldg(&b2[0]));
        float z1 = fmaf(dv, a.y, __ldg(&b2[1]));
        float m = fmaxf(z0, z1);
        float lse = m + logf(expf(z0 - m) + expf(z1 - m));
        reinterpret_cast<float2*>(out)[i] = make_float2(z0 - lse, z1 - lse);
    }
}

// ---------------- launch ----------------

extern "C" void kernel_launch(void* const* d_in, const int* in_sizes, int n_in,
                              void* d_out, int out_size) {
    const float* x  = (const float*)d_in[0];
    const int*   ei = (const int*)  d_in[1];
    const float* W1 = (const float*)d_in[2];
    const float* b1 = (const float*)d_in[3];
    const float* W2 = (const float*)d_in[4];
    const float* b2 = (const float*)d_in[5];
    int n = in_sizes[0];        // 100000
    int E = in_sizes[1] / 2;
    const int* src = ei;
    const int* dst = ei + E;

    const int HIST_BYTES = HWORDS * 4;  // 200 KB
    cudaFuncSetAttribute(k_deg, cudaFuncAttributeMaxDynamicSharedMemorySize, HIST_BYTES);

    int e8   = (E + 7) / 8;
    int nb_e = (e8 + 255) / 256;

    k_deg  <<<148, 1024, HIST_BYTES>>>(dst, E);
    k_node1<<<148, 512>>>(x);
    k_agg1 <<<nb_e, 256>>>(src, dst, E);
    k_node2<<<148, 512>>>(W1, b1, W2, n);
    k_agg2 <<<nb_e, 256>>>(src, dst, E);
    k_out  <<<148, 512>>>(b2, (float*)d_out, n);
}